// round 1
// baseline (speedup 1.0000x reference)
#include <cuda_runtime.h>
#include <math.h>

#define B 32
#define C 256
#define H 64
#define W 64
#define MIP 8
#define HID 256
#define OUTD 14

// scratch (device globals; no allocation)
__device__ float g_y[B * C * 128];     // concat(row-means, col-means)
__device__ float g_y2[B * MIP * 128];  // squeezed + bn + hswish
__device__ float g_p[B * C];           // attention-weighted pooled features

// ---------------------------------------------------------------------------
// K1: per-(b,c) 64x64 tile -> 64 row means + 64 col means
// ---------------------------------------------------------------------------
__global__ void k1_rowcol(const float* __restrict__ x) {
    int bc = blockIdx.x;
    int tid = threadIdx.x;
    const float4* xt = (const float4*)(x + (size_t)bc * 4096);
    __shared__ float tile[64 * 65];  // pad 65: conflict-free row & col reads

#pragma unroll
    for (int k = 0; k < 4; k++) {
        int i = tid + k * 256;          // 0..1023 float4s
        float4 v = xt[i];
        int r = i >> 4;
        int c = (i & 15) << 2;
        float* d = &tile[r * 65 + c];
        d[0] = v.x; d[1] = v.y; d[2] = v.z; d[3] = v.w;
    }
    __syncthreads();

    if (tid < 64) {
        float s = 0.f;
#pragma unroll
        for (int j = 0; j < 64; j++) s += tile[tid * 65 + j];
        g_y[(size_t)bc * 128 + tid] = s * (1.0f / 64.0f);          // xh[h]
    } else if (tid < 128) {
        int w = tid - 64;
        float s = 0.f;
#pragma unroll
        for (int h = 0; h < 64; h++) s += tile[h * 65 + w];
        g_y[(size_t)bc * 128 + 64 + w] = s * (1.0f / 64.0f);       // xw[w]
    }
}

// ---------------------------------------------------------------------------
// K2: y2[b][m][l] = hswish(bn( sum_c w1[m][c] * y[b][c][l] ))
// ---------------------------------------------------------------------------
__global__ void k2_squeeze(const float* __restrict__ w1,
                           const float* __restrict__ bng,
                           const float* __restrict__ bnb,
                           const float* __restrict__ bnm,
                           const float* __restrict__ bnv) {
    int b = blockIdx.x;
    int tid = threadIdx.x;
    __shared__ float w1s[MIP * C];
    for (int i = tid; i < MIP * C; i += 256) w1s[i] = w1[i];
    __syncthreads();

    const float* yb = g_y + (size_t)b * C * 128;
    int l = tid & 127;
    int m0 = tid >> 7;  // 0 or 1
    float acc[4] = {0.f, 0.f, 0.f, 0.f};
    for (int c = 0; c < C; c++) {
        float yv = yb[c * 128 + l];
#pragma unroll
        for (int k = 0; k < 4; k++) acc[k] += w1s[(m0 + 2 * k) * C + c] * yv;
    }
#pragma unroll
    for (int k = 0; k < 4; k++) {
        int m = m0 + 2 * k;
        float sc = bng[m] * rsqrtf(bnv[m] + 1e-5f);
        float v = (acc[k] - bnm[m]) * sc + bnb[m];
        float hs = v * fminf(fmaxf(v + 3.0f, 0.0f), 6.0f) * (1.0f / 6.0f);
        g_y2[b * (MIP * 128) + m * 128 + l] = hs;
    }
}

// ---------------------------------------------------------------------------
// K3: per-(b,c): 128 sigmoid attentions, then p[b][c] = mean(x * ah * aw)
// ---------------------------------------------------------------------------
__global__ void k3_pool(const float* __restrict__ x,
                        const float* __restrict__ wh,
                        const float* __restrict__ ww) {
    int bc = blockIdx.x;
    int b = bc >> 8;
    int c = bc & 255;
    int tid = threadIdx.x;
    __shared__ float att[128];  // [0..63]=a_h, [64..127]=a_w
    __shared__ float red[8];

    if (tid < 128) {
        const float* wm = (tid < 64) ? (wh + c * MIP) : (ww + c * MIP);
        const float* y2b = g_y2 + b * (MIP * 128);
        float s = 0.f;
#pragma unroll
        for (int m = 0; m < MIP; m++) s += wm[m] * y2b[m * 128 + tid];
        att[tid] = 1.0f / (1.0f + __expf(-s));
    }
    __syncthreads();

    const float4* xt = (const float4*)(x + (size_t)bc * 4096);
    float acc = 0.f;
#pragma unroll
    for (int k = 0; k < 4; k++) {
        int i = tid + k * 256;
        float4 v = xt[i];
        int r = i >> 4;
        int c4 = (i & 15) << 2;
        float ah = att[r];
        acc += ah * (v.x * att[64 + c4] + v.y * att[64 + c4 + 1] +
                     v.z * att[64 + c4 + 2] + v.w * att[64 + c4 + 3]);
    }
    for (int off = 16; off; off >>= 1) acc += __shfl_down_sync(0xffffffffu, acc, off);
    if ((tid & 31) == 0) red[tid >> 5] = acc;
    __syncthreads();
    if (tid == 0) {
        float t = 0.f;
#pragma unroll
        for (int i = 0; i < 8; i++) t += red[i];
        g_p[bc] = t * (1.0f / 4096.0f);
    }
}

// ---------------------------------------------------------------------------
// Geometry (double precision; 64 independent tiny problems)
// ---------------------------------------------------------------------------
__device__ __forceinline__ double softplus_d(double x) {
    return fmax(x, 0.0) + log1p(exp(-fabs(x)));
}

__device__ void geometry(int b, int e, const float* raws,
                         const float* __restrict__ Km,
                         const float* __restrict__ irisR,
                         float* __restrict__ out) {
    double t0 = raws[e * 7 + 0], t1 = raws[e * 7 + 1], t2 = raws[e * 7 + 2];
    double t3 = raws[e * 7 + 3], t4 = raws[e * 7 + 4], t5 = raws[e * 7 + 5];
    double t6 = raws[e * 7 + 6];

    double cx = t0, cy = t1;
    double ea = softplus_d(t2) + 1e-6;
    double eb = softplus_d(t3) + 1e-6;
    double nrm = sqrt(t4 * t4 + t5 * t5);
    double cth = t4 / (nrm + 1e-8);
    double sth = t5 / (nrm + 1e-8);
    double delta = 0.3 * tanh(t6);

    int be = b * 2 + e;
    // ellipse
    out[be * 6 + 0] = (float)cx;
    out[be * 6 + 1] = (float)cy;
    out[be * 6 + 2] = (float)ea;
    out[be * 6 + 3] = (float)eb;
    out[be * 6 + 4] = (float)cth;
    out[be * 6 + 5] = (float)sth;
    // delta_cm
    out[384 + be] = (float)delta;

    double theta = atan2(sth, cth);
    double ct = cos(theta), st = sin(theta);
    double ia2 = 1.0 / (ea * ea), ib2 = 1.0 / (eb * eb);
    double A11 = ct * ct * ia2 + st * st * ib2;
    double A22 = st * st * ia2 + ct * ct * ib2;
    double A12 = ct * st * (ia2 - ib2);
    double axv = A11 * cx + A12 * cy;
    double ayv = A12 * cx + A22 * cy;
    double cAc = A11 * cx * cx + 2.0 * A12 * cx * cy + A22 * cy * cy;

    double M[3][3] = {{A11, A12, -axv}, {A12, A22, -ayv}, {-axv, -ayv, cAc - 1.0}};
    double Kd[3][3];
#pragma unroll
    for (int j = 0; j < 3; j++)
#pragma unroll
        for (int i = 0; i < 3; i++) Kd[j][i] = (double)Km[b * 9 + j * 3 + i];

    double Cn[3][3];
#pragma unroll
    for (int i = 0; i < 3; i++)
#pragma unroll
        for (int l = 0; l < 3; l++) {
            double s = 0.0;
#pragma unroll
            for (int j = 0; j < 3; j++) {
                double r = 0.0;
#pragma unroll
                for (int k = 0; k < 3; k++) r += M[j][k] * Kd[k][l];
                s += Kd[j][i] * r;
            }
            Cn[i][l] = s;
        }

    double a00 = Cn[0][0], a01 = Cn[0][1], a10 = Cn[1][0], a11 = Cn[1][1];
    double u0 = Cn[0][2], u1 = Cn[1][2];
    double det = a00 * a11 - a01 * a10;
    double mu0 = (-u0 * a11 + a01 * u1) / det;
    double mu1 = (a10 * u0 - a00 * u1) / det;

    // ---- slaev2 (LAPACK 2x2 symmetric eigh, lower triangle: a00, a10, a11)
    double a = a00, bb = a10, cc = a11;
    double sm = a + cc, df = a - cc, adf = fabs(df), tb = bb + bb, ab = fabs(tb);
    double rt;
    if (adf > ab) { double q = ab / adf; rt = adf * sqrt(1.0 + q * q); }
    else if (adf < ab) { double q = adf / ab; rt = ab * sqrt(1.0 + q * q); }
    else rt = ab * sqrt(2.0);
    double rt1, rt2; int sgn1;
    if (sm < 0.0) { rt1 = 0.5 * (sm - rt); sgn1 = -1; rt2 = (a / rt1) * cc - (bb / rt1) * bb; }
    else if (sm > 0.0) { rt1 = 0.5 * (sm + rt); sgn1 = 1; rt2 = (a / rt1) * cc - (bb / rt1) * bb; }
    else { rt1 = 0.5 * rt; rt2 = -0.5 * rt; sgn1 = 1; }
    double cs; int sgn2;
    if (df >= 0.0) { cs = df + rt; sgn2 = 1; } else { cs = df - rt; sgn2 = -1; }
    double acs = fabs(cs), cs1, sn1;
    if (acs > ab) { double ctn = -tb / cs; sn1 = 1.0 / sqrt(1.0 + ctn * ctn); cs1 = ctn * sn1; }
    else {
        if (ab == 0.0) { cs1 = 1.0; sn1 = 0.0; }
        else { double tn = -cs / tb; cs1 = 1.0 / sqrt(1.0 + tn * tn); sn1 = tn * cs1; }
    }
    if (sgn1 == sgn2) { double tt = cs1; cs1 = -sn1; sn1 = tt; }
    // ascending order: rt1 is the eigenvalue of larger magnitude
    double lam0, lam1, v0, v1;
    if (rt1 <= rt2) { lam0 = rt1; lam1 = rt2; v0 = cs1; v1 = sn1; }
    else            { lam0 = rt2; lam1 = rt1; v0 = -sn1; v1 = cs1; }

    double a_n = 1.0 / sqrt(fmax(lam0, 1e-12));
    double b_n = 1.0 / sqrt(fmax(lam1, 1e-12));
    a_n = fmax(a_n, 1e-6);
    double R = (double)irisR[b];
    double z = fmin(fmax(R / a_n, 0.5), 1000.0);

    double rn = sqrt(mu0 * mu0 + mu1 * mu1 + 1.0) + 1e-8;
    double icx = mu0 / rn * z, icy = mu1 / rn * z, icz = (1.0 / rn) * z;

    double tilt = acos(fmin(fmax(b_n / a_n, 0.0), 1.0));
    double thn = atan2(v1, v0);
    double ck = cos(thn), sk = sin(thn);
    double nk = sqrt(ck * ck + sk * sk) + 1e-8;
    double kx = ck / nk, ky = sk / nk;  // kz = 0
    double ctl = cos(tilt), stl = sin(tilt);
    // normal ∝ z_ax*ctl + (k × z)*stl   (k·z = 0)
    double nx = ky * stl, ny = -kx * stl, nz = ctl;
    double nn = sqrt(nx * nx + ny * ny + nz * nz) + 1e-8;
    nx /= nn; ny /= nn; nz /= nn;

    double px = icx + delta * nx, py = icy + delta * ny, pz = icz + delta * nz;

    out[448 + be * 3 + 0] = (float)icx;
    out[448 + be * 3 + 1] = (float)icy;
    out[448 + be * 3 + 2] = (float)icz;
    out[640 + be * 3 + 0] = (float)nx;
    out[640 + be * 3 + 1] = (float)ny;
    out[640 + be * 3 + 2] = (float)nz;
    out[832 + be * 3 + 0] = (float)px;
    out[832 + be * 3 + 1] = (float)py;
    out[832 + be * 3 + 2] = (float)pz;
    out[1024 + be] = (float)z;
}

// ---------------------------------------------------------------------------
// K4: fc1 + bn + relu + fc_out + geometry, one block per batch element
// ---------------------------------------------------------------------------
__global__ void k4_head(const float* __restrict__ fc1w, const float* __restrict__ fc1b,
                        const float* __restrict__ bn1g, const float* __restrict__ bn1b,
                        const float* __restrict__ bn1m, const float* __restrict__ bn1v,
                        const float* __restrict__ fow, const float* __restrict__ fob,
                        const float* __restrict__ Km, const float* __restrict__ irisR,
                        float* __restrict__ out) {
    int b = blockIdx.x;
    int tid = threadIdx.x;
    __shared__ float ps[HID];
    __shared__ float hs[HID];
    __shared__ float raws[OUTD];

    ps[tid] = g_p[b * C + tid];
    __syncthreads();

    int warp = tid >> 5, lane = tid & 31;
    for (int jo = 0; jo < 32; jo++) {
        int j = warp * 32 + jo;
        float part = 0.f;
#pragma unroll
        for (int k = 0; k < 8; k++) {
            int c = lane + 32 * k;
            part += ps[c] * fc1w[j * C + c];
        }
        for (int off = 16; off; off >>= 1) part += __shfl_down_sync(0xffffffffu, part, off);
        if (lane == 0) {
            float acc = part + fc1b[j];
            float sc = bn1g[j] * rsqrtf(bn1v[j] + 1e-5f);
            float v = (acc - bn1m[j]) * sc + bn1b[j];
            hs[j] = fmaxf(v, 0.0f);
        }
    }
    __syncthreads();

    for (int o = warp; o < OUTD; o += 8) {
        float part = 0.f;
#pragma unroll
        for (int k = 0; k < 8; k++) {
            int c = lane + 32 * k;
            part += hs[c] * fow[o * HID + c];
        }
        for (int off = 16; off; off >>= 1) part += __shfl_down_sync(0xffffffffu, part, off);
        if (lane == 0) raws[o] = part + fob[o];
    }
    __syncthreads();

    if (tid < 2) geometry(b, tid, raws, Km, irisR, out);
}

// ---------------------------------------------------------------------------
extern "C" void kernel_launch(void* const* d_in, const int* in_sizes, int n_in,
                              void* d_out, int out_size) {
    const float* x     = (const float*)d_in[0];
    const float* Km    = (const float*)d_in[1];
    const float* irisR = (const float*)d_in[2];
    const float* ca_w1 = (const float*)d_in[3];
    const float* ca_bn_g = (const float*)d_in[4];
    const float* ca_bn_b = (const float*)d_in[5];
    const float* ca_bn_m = (const float*)d_in[6];
    const float* ca_bn_v = (const float*)d_in[7];
    const float* ca_wh = (const float*)d_in[8];
    const float* ca_ww = (const float*)d_in[9];
    const float* fc1_w = (const float*)d_in[10];
    const float* fc1_b = (const float*)d_in[11];
    const float* bn1_g = (const float*)d_in[12];
    const float* bn1_b = (const float*)d_in[13];
    const float* bn1_m = (const float*)d_in[14];
    const float* bn1_v = (const float*)d_in[15];
    const float* fc_out_w = (const float*)d_in[16];
    const float* fc_out_b = (const float*)d_in[17];
    float* out = (float*)d_out;

    k1_rowcol<<<B * C, 256>>>(x);
    k2_squeeze<<<B, 256>>>(ca_w1, ca_bn_g, ca_bn_b, ca_bn_m, ca_bn_v);
    k3_pool<<<B * C, 256>>>(x, ca_wh, ca_ww);
    k4_head<<<B, 256>>>(fc1_w, fc1_b, bn1_g, bn1_b, bn1_m, bn1_v,
                        fc_out_w, fc_out_b, Km, irisR, out);
}

// round 2
// speedup vs baseline: 1.1808x; 1.1808x over previous
#include <cuda_runtime.h>
#include <math.h>

#define B 32
#define C 256
#define H 64
#define W 64
#define MIP 8
#define HID 256
#define OUTD 14

// scratch (device globals; no allocation)
__device__ float g_y[B * C * 128];     // concat(row-means, col-means)
__device__ float g_y2[B * MIP * 128];  // squeezed + bn + hswish
__device__ float g_p[B * C];           // attention-weighted pooled features

// ---------------------------------------------------------------------------
// K1: per-(b,c) 64x64 tile -> 64 row means + 64 col means
// ---------------------------------------------------------------------------
__global__ void k1_rowcol(const float* __restrict__ x) {
    int bc = blockIdx.x;
    int tid = threadIdx.x;
    const float4* xt = (const float4*)(x + (size_t)bc * 4096);
    __shared__ float tile[64 * 65];  // pad 65: conflict-free row & col reads

#pragma unroll
    for (int k = 0; k < 4; k++) {
        int i = tid + k * 256;          // 0..1023 float4s
        float4 v = xt[i];
        int r = i >> 4;
        int c = (i & 15) << 2;
        float* d = &tile[r * 65 + c];
        d[0] = v.x; d[1] = v.y; d[2] = v.z; d[3] = v.w;
    }
    __syncthreads();

    if (tid < 64) {
        float s = 0.f;
#pragma unroll
        for (int j = 0; j < 64; j++) s += tile[tid * 65 + j];
        g_y[(size_t)bc * 128 + tid] = s * (1.0f / 64.0f);          // xh[h]
    } else if (tid < 128) {
        int w = tid - 64;
        float s = 0.f;
#pragma unroll
        for (int h = 0; h < 64; h++) s += tile[h * 65 + w];
        g_y[(size_t)bc * 128 + 64 + w] = s * (1.0f / 64.0f);       // xw[w]
    }
}

// ---------------------------------------------------------------------------
// K2: y2[b][m][l] = hswish(bn( sum_c w1[m][c] * y[b][c][l] ))
// grid = (B, 4): each block handles 32 l-positions; threads = 8m x 32l
// ---------------------------------------------------------------------------
__global__ void k2_squeeze(const float* __restrict__ w1,
                           const float* __restrict__ bng,
                           const float* __restrict__ bnb,
                           const float* __restrict__ bnm,
                           const float* __restrict__ bnv) {
    int b = blockIdx.x;
    int lbase = blockIdx.y * 32;
    int tid = threadIdx.x;
    int m = tid >> 5;        // warp = one m
    int li = tid & 31;
    int l = lbase + li;

    __shared__ float w1s[MIP * C];
    for (int i = tid; i < MIP * C; i += 256) w1s[i] = w1[i];
    __syncthreads();

    const float* yb = g_y + (size_t)b * C * 128;
    float acc = 0.f;
#pragma unroll 8
    for (int c = 0; c < C; c++) {
        acc += w1s[m * C + c] * yb[c * 128 + l];
    }
    float sc = bng[m] * rsqrtf(bnv[m] + 1e-5f);
    float v = (acc - bnm[m]) * sc + bnb[m];
    float hs = v * fminf(fmaxf(v + 3.0f, 0.0f), 6.0f) * (1.0f / 6.0f);
    g_y2[b * (MIP * 128) + m * 128 + l] = hs;
}

// ---------------------------------------------------------------------------
// K3: per-(b,c): 128 sigmoid attentions, then p[b][c] = mean(x * ah * aw)
// ---------------------------------------------------------------------------
__global__ void k3_pool(const float* __restrict__ x,
                        const float* __restrict__ wh,
                        const float* __restrict__ ww) {
    int bc = blockIdx.x;
    int b = bc >> 8;
    int c = bc & 255;
    int tid = threadIdx.x;
    __shared__ float att[128];  // [0..63]=a_h, [64..127]=a_w
    __shared__ float red[8];

    if (tid < 128) {
        const float* wm = (tid < 64) ? (wh + c * MIP) : (ww + c * MIP);
        const float* y2b = g_y2 + b * (MIP * 128);
        float s = 0.f;
#pragma unroll
        for (int m = 0; m < MIP; m++) s += wm[m] * y2b[m * 128 + tid];
        att[tid] = 1.0f / (1.0f + __expf(-s));
    }
    __syncthreads();

    const float4* xt = (const float4*)(x + (size_t)bc * 4096);
    float acc = 0.f;
#pragma unroll
    for (int k = 0; k < 4; k++) {
        int i = tid + k * 256;
        float4 v = xt[i];
        int r = i >> 4;
        int c4 = (i & 15) << 2;
        float ah = att[r];
        acc += ah * (v.x * att[64 + c4] + v.y * att[64 + c4 + 1] +
                     v.z * att[64 + c4 + 2] + v.w * att[64 + c4 + 3]);
    }
    for (int off = 16; off; off >>= 1) acc += __shfl_down_sync(0xffffffffu, acc, off);
    if ((tid & 31) == 0) red[tid >> 5] = acc;
    __syncthreads();
    if (tid == 0) {
        float t = 0.f;
#pragma unroll
        for (int i = 0; i < 8; i++) t += red[i];
        g_p[bc] = t * (1.0f / 4096.0f);
    }
}

// ---------------------------------------------------------------------------
// Geometry — transcendental-free except tanhf/softplus (float).
// Conic -> solve -> slaev2 chain kept in double (pure DFMA/sqrt, cheap).
// ---------------------------------------------------------------------------
__device__ __forceinline__ float softplus_f(float x) {
    return fmaxf(x, 0.0f) + log1pf(__expf(-fabsf(x)));
}

__device__ void geometry(int b, int e, const float* raws,
                         const float* __restrict__ Km,
                         const float* __restrict__ irisR,
                         float* __restrict__ out) {
    float t0 = raws[e * 7 + 0], t1 = raws[e * 7 + 1], t2 = raws[e * 7 + 2];
    float t3 = raws[e * 7 + 3], t4 = raws[e * 7 + 4], t5 = raws[e * 7 + 5];
    float t6 = raws[e * 7 + 6];

    float cx = t0, cy = t1;
    float ea = softplus_f(t2) + 1e-6f;
    float eb = softplus_f(t3) + 1e-6f;
    float nrm = sqrtf(t4 * t4 + t5 * t5);
    float cth = t4 / (nrm + 1e-8f);
    float sth = t5 / (nrm + 1e-8f);
    float delta = 0.3f * tanhf(t6);

    int be = b * 2 + e;
    out[be * 6 + 0] = cx;
    out[be * 6 + 1] = cy;
    out[be * 6 + 2] = ea;
    out[be * 6 + 3] = eb;
    out[be * 6 + 4] = cth;
    out[be * 6 + 5] = sth;
    out[384 + be] = delta;

    // ct = cos(atan2(sth,cth)) = t4/nrm (renormalized); guard nrm==0 -> theta=0
    float ct_f, st_f;
    if (nrm > 0.f) { ct_f = t4 / nrm; st_f = t5 / nrm; }
    else           { ct_f = 1.f;      st_f = 0.f; }

    double ct = ct_f, st = st_f;
    double ia2 = 1.0 / ((double)ea * ea), ib2 = 1.0 / ((double)eb * eb);
    double A11 = ct * ct * ia2 + st * st * ib2;
    double A22 = st * st * ia2 + ct * ct * ib2;
    double A12 = ct * st * (ia2 - ib2);
    double axv = A11 * cx + A12 * cy;
    double ayv = A12 * cx + A22 * cy;
    double cAc = A11 * (double)cx * cx + 2.0 * A12 * (double)cx * cy + A22 * (double)cy * cy;

    double M[3][3] = {{A11, A12, -axv}, {A12, A22, -ayv}, {-axv, -ayv, cAc - 1.0}};
    double Kd[3][3];
#pragma unroll
    for (int j = 0; j < 3; j++)
#pragma unroll
        for (int i = 0; i < 3; i++) Kd[j][i] = (double)Km[b * 9 + j * 3 + i];

    double Cn[3][3];
#pragma unroll
    for (int i = 0; i < 3; i++)
#pragma unroll
        for (int l = 0; l < 3; l++) {
            double s = 0.0;
#pragma unroll
            for (int j = 0; j < 3; j++) {
                double r = 0.0;
#pragma unroll
                for (int k = 0; k < 3; k++) r += M[j][k] * Kd[k][l];
                s += Kd[j][i] * r;
            }
            Cn[i][l] = s;
        }

    double a00 = Cn[0][0], a01 = Cn[0][1], a10 = Cn[1][0], a11 = Cn[1][1];
    double u0 = Cn[0][2], u1 = Cn[1][2];
    double det = a00 * a11 - a01 * a10;
    double mu0 = (-u0 * a11 + a01 * u1) / det;
    double mu1 = (a10 * u0 - a00 * u1) / det;

    // ---- slaev2 (LAPACK 2x2 symmetric eigh; lower triangle a00, a10, a11)
    double a = a00, bb = a10, cc = a11;
    double sm = a + cc, df = a - cc, adf = fabs(df), tb = bb + bb, ab = fabs(tb);
    double rt;
    if (adf > ab) { double q = ab / adf; rt = adf * sqrt(1.0 + q * q); }
    else if (adf < ab) { double q = adf / ab; rt = ab * sqrt(1.0 + q * q); }
    else rt = ab * sqrt(2.0);
    double rt1, rt2; int sgn1;
    if (sm < 0.0) { rt1 = 0.5 * (sm - rt); sgn1 = -1; rt2 = (a / rt1) * cc - (bb / rt1) * bb; }
    else if (sm > 0.0) { rt1 = 0.5 * (sm + rt); sgn1 = 1; rt2 = (a / rt1) * cc - (bb / rt1) * bb; }
    else { rt1 = 0.5 * rt; rt2 = -0.5 * rt; sgn1 = 1; }
    double cs; int sgn2;
    if (df >= 0.0) { cs = df + rt; sgn2 = 1; } else { cs = df - rt; sgn2 = -1; }
    double acs = fabs(cs), cs1, sn1;
    if (acs > ab) { double ctn = -tb / cs; sn1 = 1.0 / sqrt(1.0 + ctn * ctn); cs1 = ctn * sn1; }
    else {
        if (ab == 0.0) { cs1 = 1.0; sn1 = 0.0; }
        else { double tn = -cs / tb; cs1 = 1.0 / sqrt(1.0 + tn * tn); sn1 = tn * cs1; }
    }
    if (sgn1 == sgn2) { double tt = cs1; cs1 = -sn1; sn1 = tt; }
    // ascending eigenvalue order
    double lam0, lam1, v0, v1;
    if (rt1 <= rt2) { lam0 = rt1; lam1 = rt2; v0 = cs1; v1 = sn1; }
    else            { lam0 = rt2; lam1 = rt1; v0 = -sn1; v1 = cs1; }

    double a_n = 1.0 / sqrt(fmax(lam0, 1e-12));
    double b_n = 1.0 / sqrt(fmax(lam1, 1e-12));
    a_n = fmax(a_n, 1e-6);
    double R = (double)irisR[b];
    double z = fmin(fmax(R / a_n, 0.5), 1000.0);

    double rn = sqrt(mu0 * mu0 + mu1 * mu1 + 1.0) + 1e-8;
    double icx = mu0 / rn * z, icy = mu1 / rn * z, icz = (1.0 / rn) * z;

    // tilt = acos(clip(b_n/a_n,0,1)) -> ctl = clipped ratio, stl = sqrt(1-ctl^2)
    double ctl = fmin(fmax(b_n / a_n, 0.0), 1.0);
    double stl = sqrt(fmax(1.0 - ctl * ctl, 0.0));
    // k = (cos(thn), sin(thn), 0)/(1+1e-8) with (v0,v1) already unit
    double hyp = sqrt(v0 * v0 + v1 * v1);
    double kx = v0 / hyp, ky = v1 / hyp;
    // normal ∝ z*ctl + (k × z)*stl ; k·z = 0
    double nx = ky * stl, ny = -kx * stl, nz = ctl;
    double nn = sqrt(nx * nx + ny * ny + nz * nz) + 1e-8;
    nx /= nn; ny /= nn; nz /= nn;

    double px = icx + delta * nx, py = icy + delta * ny, pz = icz + delta * nz;

    out[448 + be * 3 + 0] = (float)icx;
    out[448 + be * 3 + 1] = (float)icy;
    out[448 + be * 3 + 2] = (float)icz;
    out[640 + be * 3 + 0] = (float)nx;
    out[640 + be * 3 + 1] = (float)ny;
    out[640 + be * 3 + 2] = (float)nz;
    out[832 + be * 3 + 0] = (float)px;
    out[832 + be * 3 + 1] = (float)py;
    out[832 + be * 3 + 2] = (float)pz;
    out[1024 + be] = (float)z;
}

// ---------------------------------------------------------------------------
// K4: fc1 (smem-staged GEMV, one output/thread) + bn + relu + fc_out + geometry
// ---------------------------------------------------------------------------
__global__ void k4_head(const float* __restrict__ fc1w, const float* __restrict__ fc1b,
                        const float* __restrict__ bn1g, const float* __restrict__ bn1b,
                        const float* __restrict__ bn1m, const float* __restrict__ bn1v,
                        const float* __restrict__ fow, const float* __restrict__ fob,
                        const float* __restrict__ Km, const float* __restrict__ irisR,
                        float* __restrict__ out) {
    int b = blockIdx.x;
    int tid = threadIdx.x;
    __shared__ float ps[HID];
    __shared__ float hs[HID];
    __shared__ float raws[OUTD];
    __shared__ float wt[256 * 33];  // padded weight tile (33: bank-conflict-free)

    ps[tid] = g_p[b * C + tid];
    __syncthreads();

    // fc1: thread tid owns output j = tid; stage 32-wide column chunks of W
    float acc = 0.f;
#pragma unroll 1
    for (int cc = 0; cc < 8; cc++) {
#pragma unroll
        for (int k = 0; k < 32; k++) {
            int i = tid + k * 256;      // 0..8191
            int j = i >> 5, u = i & 31;
            wt[j * 33 + u] = fc1w[j * C + cc * 32 + u];
        }
        __syncthreads();
#pragma unroll
        for (int u = 0; u < 32; u++)
            acc += ps[cc * 32 + u] * wt[tid * 33 + u];
        __syncthreads();
    }
    {
        float v = acc + fc1b[tid];
        float sc = bn1g[tid] * rsqrtf(bn1v[tid] + 1e-5f);
        v = (v - bn1m[tid]) * sc + bn1b[tid];
        hs[tid] = fmaxf(v, 0.0f);
    }
    __syncthreads();

    int warp = tid >> 5, lane = tid & 31;
    for (int o = warp; o < OUTD; o += 8) {
        float part = 0.f;
#pragma unroll
        for (int k = 0; k < 8; k++) {
            int c = lane + 32 * k;
            part += hs[c] * fow[o * HID + c];
        }
        for (int off = 16; off; off >>= 1) part += __shfl_down_sync(0xffffffffu, part, off);
        if (lane == 0) raws[o] = part + fob[o];
    }
    __syncthreads();

    if (tid < 2) geometry(b, tid, raws, Km, irisR, out);
}

// ---------------------------------------------------------------------------
extern "C" void kernel_launch(void* const* d_in, const int* in_sizes, int n_in,
                              void* d_out, int out_size) {
    const float* x     = (const float*)d_in[0];
    const float* Km    = (const float*)d_in[1];
    const float* irisR = (const float*)d_in[2];
    const float* ca_w1 = (const float*)d_in[3];
    const float* ca_bn_g = (const float*)d_in[4];
    const float* ca_bn_b = (const float*)d_in[5];
    const float* ca_bn_m = (const float*)d_in[6];
    const float* ca_bn_v = (const float*)d_in[7];
    const float* ca_wh = (const float*)d_in[8];
    const float* ca_ww = (const float*)d_in[9];
    const float* fc1_w = (const float*)d_in[10];
    const float* fc1_b = (const float*)d_in[11];
    const float* bn1_g = (const float*)d_in[12];
    const float* bn1_b = (const float*)d_in[13];
    const float* bn1_m = (const float*)d_in[14];
    const float* bn1_v = (const float*)d_in[15];
    const float* fc_out_w = (const float*)d_in[16];
    const float* fc_out_b = (const float*)d_in[17];
    float* out = (float*)d_out;

    k1_rowcol<<<B * C, 256>>>(x);
    dim3 g2(B, 4);
    k2_squeeze<<<g2, 256>>>(ca_w1, ca_bn_g, ca_bn_b, ca_bn_m, ca_bn_v);
    k3_pool<<<B * C, 256>>>(x, ca_wh, ca_ww);
    k4_head<<<B, 256>>>(fc1_w, fc1_b, bn1_g, bn1_b, bn1_m, bn1_v,
                        fc_out_w, fc_out_b, Km, irisR, out);
}

// round 3
// speedup vs baseline: 1.5482x; 1.3112x over previous
#include <cuda_runtime.h>
#include <math.h>

#define B 32
#define C 256
#define H 64
#define W 64
#define MIP 8
#define HID 256
#define OUTD 14

// scratch (device globals; no allocation)
__device__ float g_y[B * C * 128];     // concat(row-means, col-means)
__device__ float g_y2[B * MIP * 128];  // squeezed + bn + hswish
__device__ float g_p[B * C];           // attention-weighted pooled features
__device__ float g_h[B * HID];         // fc1+bn+relu hidden

// ---------------------------------------------------------------------------
// K1: per-(b,c) 64x64 tile -> 64 row means + 64 col means
// ---------------------------------------------------------------------------
__global__ void k1_rowcol(const float* __restrict__ x) {
    int bc = blockIdx.x;
    int tid = threadIdx.x;
    const float4* xt = (const float4*)(x + (size_t)bc * 4096);
    __shared__ float tile[64 * 65];  // pad 65: conflict-free row & col reads

#pragma unroll
    for (int k = 0; k < 4; k++) {
        int i = tid + k * 256;          // 0..1023 float4s
        float4 v = xt[i];
        int r = i >> 4;
        int c = (i & 15) << 2;
        float* d = &tile[r * 65 + c];
        d[0] = v.x; d[1] = v.y; d[2] = v.z; d[3] = v.w;
    }
    __syncthreads();

    if (tid < 64) {
        float s = 0.f;
#pragma unroll
        for (int j = 0; j < 64; j++) s += tile[tid * 65 + j];
        g_y[(size_t)bc * 128 + tid] = s * (1.0f / 64.0f);          // xh[h]
    } else if (tid < 128) {
        int w = tid - 64;
        float s = 0.f;
#pragma unroll
        for (int h = 0; h < 64; h++) s += tile[h * 65 + w];
        g_y[(size_t)bc * 128 + 64 + w] = s * (1.0f / 64.0f);       // xw[w]
    }
}

// ---------------------------------------------------------------------------
// K2: y2[b][m][l] = hswish(bn( sum_c w1[m][c] * y[b][c][l] ))
// grid = (B, 4): each block handles 32 l-positions; warp = one m
// ---------------------------------------------------------------------------
__global__ void k2_squeeze(const float* __restrict__ w1,
                           const float* __restrict__ bng,
                           const float* __restrict__ bnb,
                           const float* __restrict__ bnm,
                           const float* __restrict__ bnv) {
    int b = blockIdx.x;
    int lbase = blockIdx.y * 32;
    int tid = threadIdx.x;
    int m = tid >> 5;
    int li = tid & 31;
    int l = lbase + li;

    __shared__ float w1s[MIP * C];
    for (int i = tid; i < MIP * C; i += 256) w1s[i] = w1[i];
    __syncthreads();

    const float* yb = g_y + (size_t)b * C * 128;
    float acc = 0.f;
#pragma unroll 8
    for (int c = 0; c < C; c++) {
        acc += w1s[m * C + c] * yb[c * 128 + l];
    }
    float sc = bng[m] * rsqrtf(bnv[m] + 1e-5f);
    float v = (acc - bnm[m]) * sc + bnb[m];
    float hs = v * fminf(fmaxf(v + 3.0f, 0.0f), 6.0f) * (1.0f / 6.0f);
    g_y2[b * (MIP * 128) + m * 128 + l] = hs;
}

// ---------------------------------------------------------------------------
// K3: per-(b,c): 128 sigmoid attentions, then p[b][c] = mean(x * ah * aw)
// REVERSE block order: k1 left the tail of x resident in L2 (134MB vs 126MB);
// reading back-to-front makes the second pass mostly L2 hits.
// ---------------------------------------------------------------------------
__global__ void k3_pool(const float* __restrict__ x,
                        const float* __restrict__ wh,
                        const float* __restrict__ ww) {
    int bc = (B * C - 1) - blockIdx.x;
    int b = bc >> 8;
    int c = bc & 255;
    int tid = threadIdx.x;
    __shared__ float att[128];  // [0..63]=a_h, [64..127]=a_w
    __shared__ float red[8];

    if (tid < 128) {
        const float* wm = (tid < 64) ? (wh + c * MIP) : (ww + c * MIP);
        const float* y2b = g_y2 + b * (MIP * 128);
        float s = 0.f;
#pragma unroll
        for (int m = 0; m < MIP; m++) s += wm[m] * y2b[m * 128 + tid];
        att[tid] = 1.0f / (1.0f + __expf(-s));
    }
    __syncthreads();

    const float4* xt = (const float4*)(x + (size_t)bc * 4096);
    float acc = 0.f;
#pragma unroll
    for (int k = 0; k < 4; k++) {
        int i = tid + k * 256;
        float4 v = xt[i];
        int r = i >> 4;
        int c4 = (i & 15) << 2;
        float ah = att[r];
        acc += ah * (v.x * att[64 + c4] + v.y * att[64 + c4 + 1] +
                     v.z * att[64 + c4 + 2] + v.w * att[64 + c4 + 3]);
    }
    for (int off = 16; off; off >>= 1) acc += __shfl_down_sync(0xffffffffu, acc, off);
    if ((tid & 31) == 0) red[tid >> 5] = acc;
    __syncthreads();
    if (tid == 0) {
        float t = 0.f;
#pragma unroll
        for (int i = 0; i < 8; i++) t += red[i];
        g_p[bc] = t * (1.0f / 4096.0f);
    }
}

// ---------------------------------------------------------------------------
// K4a: fc1 GEMV + bn + relu. grid (B, 8): block computes 32 outputs.
// Warp computes 4 outputs; lanes stride the 256-dim reduction.
// ---------------------------------------------------------------------------
__global__ void k4a_fc1(const float* __restrict__ fc1w, const float* __restrict__ fc1b,
                        const float* __restrict__ bn1g, const float* __restrict__ bn1b,
                        const float* __restrict__ bn1m, const float* __restrict__ bn1v) {
    int b = blockIdx.x;
    int g = blockIdx.y;
    int tid = threadIdx.x;
    __shared__ float ps[C];
    ps[tid] = g_p[b * C + tid];
    __syncthreads();

    int warp = tid >> 5, lane = tid & 31;
    int j0 = g * 32 + warp * 4;
    float acc0 = 0.f, acc1 = 0.f, acc2 = 0.f, acc3 = 0.f;
#pragma unroll
    for (int k = 0; k < 8; k++) {
        int cc = lane + 32 * k;
        float pv = ps[cc];
        acc0 += pv * fc1w[(j0 + 0) * C + cc];
        acc1 += pv * fc1w[(j0 + 1) * C + cc];
        acc2 += pv * fc1w[(j0 + 2) * C + cc];
        acc3 += pv * fc1w[(j0 + 3) * C + cc];
    }
    float accs[4] = {acc0, acc1, acc2, acc3};
#pragma unroll
    for (int q = 0; q < 4; q++) {
        float v = accs[q];
        for (int off = 16; off; off >>= 1) v += __shfl_down_sync(0xffffffffu, v, off);
        if (lane == 0) {
            int j = j0 + q;
            v += fc1b[j];
            float sc = bn1g[j] * rsqrtf(bn1v[j] + 1e-5f);
            v = (v - bn1m[j]) * sc + bn1b[j];
            g_h[b * HID + j] = fmaxf(v, 0.0f);
        }
    }
}

// ---------------------------------------------------------------------------
// Geometry — all float; transcendental-free except tanhf/softplus.
// ---------------------------------------------------------------------------
__device__ __forceinline__ float softplus_f(float x) {
    return fmaxf(x, 0.0f) + log1pf(expf(-fabsf(x)));
}

__device__ void geometry(int b, int e, const float* raws,
                         const float* __restrict__ Km,
                         const float* __restrict__ irisR,
                         float* __restrict__ out) {
    float t0 = raws[e * 7 + 0], t1 = raws[e * 7 + 1], t2 = raws[e * 7 + 2];
    float t3 = raws[e * 7 + 3], t4 = raws[e * 7 + 4], t5 = raws[e * 7 + 5];
    float t6 = raws[e * 7 + 6];

    float cx = t0, cy = t1;
    float ea = softplus_f(t2) + 1e-6f;
    float eb = softplus_f(t3) + 1e-6f;
    float nrm = sqrtf(t4 * t4 + t5 * t5);
    float cth = t4 / (nrm + 1e-8f);
    float sth = t5 / (nrm + 1e-8f);
    float delta = 0.3f * tanhf(t6);

    int be = b * 2 + e;
    out[be * 6 + 0] = cx;
    out[be * 6 + 1] = cy;
    out[be * 6 + 2] = ea;
    out[be * 6 + 3] = eb;
    out[be * 6 + 4] = cth;
    out[be * 6 + 5] = sth;
    out[384 + be] = delta;

    // cos/sin(atan2(sth,cth)) == renormalized (t4,t5); guard zero
    float ct, st;
    if (nrm > 0.f) { ct = t4 / nrm; st = t5 / nrm; }
    else           { ct = 1.f;      st = 0.f; }

    float ia2 = 1.0f / (ea * ea), ib2 = 1.0f / (eb * eb);
    float A11 = ct * ct * ia2 + st * st * ib2;
    float A22 = st * st * ia2 + ct * ct * ib2;
    float A12 = ct * st * (ia2 - ib2);
    float axv = A11 * cx + A12 * cy;
    float ayv = A12 * cx + A22 * cy;
    float cAc = A11 * cx * cx + 2.0f * A12 * cx * cy + A22 * cy * cy;

    float M[3][3] = {{A11, A12, -axv}, {A12, A22, -ayv}, {-axv, -ayv, cAc - 1.0f}};
    float Kd[3][3];
#pragma unroll
    for (int j = 0; j < 3; j++)
#pragma unroll
        for (int i = 0; i < 3; i++) Kd[j][i] = Km[b * 9 + j * 3 + i];

    float Cn[3][3];
#pragma unroll
    for (int i = 0; i < 3; i++)
#pragma unroll
        for (int l = 0; l < 3; l++) {
            float s = 0.0f;
#pragma unroll
            for (int j = 0; j < 3; j++) {
                float r = 0.0f;
#pragma unroll
                for (int k = 0; k < 3; k++) r += M[j][k] * Kd[k][l];
                s += Kd[j][i] * r;
            }
            Cn[i][l] = s;
        }

    float a00 = Cn[0][0], a01 = Cn[0][1], a10 = Cn[1][0], a11 = Cn[1][1];
    float u0 = Cn[0][2], u1 = Cn[1][2];
    float det = a00 * a11 - a01 * a10;
    float mu0 = (-u0 * a11 + a01 * u1) / det;
    float mu1 = (a10 * u0 - a00 * u1) / det;

    // ---- slaev2 (LAPACK 2x2 symmetric eigh; lower triangle a00, a10, a11)
    float a = a00, bb = a10, cc = a11;
    float sm = a + cc, df = a - cc, adf = fabsf(df), tb = bb + bb, ab = fabsf(tb);
    float rt;
    if (adf > ab) { float q = ab / adf; rt = adf * sqrtf(1.0f + q * q); }
    else if (adf < ab) { float q = adf / ab; rt = ab * sqrtf(1.0f + q * q); }
    else rt = ab * sqrtf(2.0f);
    float rt1, rt2; int sgn1;
    if (sm < 0.0f) { rt1 = 0.5f * (sm - rt); sgn1 = -1; rt2 = (a / rt1) * cc - (bb / rt1) * bb; }
    else if (sm > 0.0f) { rt1 = 0.5f * (sm + rt); sgn1 = 1; rt2 = (a / rt1) * cc - (bb / rt1) * bb; }
    else { rt1 = 0.5f * rt; rt2 = -0.5f * rt; sgn1 = 1; }
    float cs; int sgn2;
    if (df >= 0.0f) { cs = df + rt; sgn2 = 1; } else { cs = df - rt; sgn2 = -1; }
    float acs = fabsf(cs), cs1, sn1;
    if (acs > ab) { float ctn = -tb / cs; sn1 = 1.0f / sqrtf(1.0f + ctn * ctn); cs1 = ctn * sn1; }
    else {
        if (ab == 0.0f) { cs1 = 1.0f; sn1 = 0.0f; }
        else { float tn = -cs / tb; cs1 = 1.0f / sqrtf(1.0f + tn * tn); sn1 = tn * cs1; }
    }
    if (sgn1 == sgn2) { float tt = cs1; cs1 = -sn1; sn1 = tt; }
    // ascending eigenvalue order
    float lam0, lam1, v0, v1;
    if (rt1 <= rt2) { lam0 = rt1; lam1 = rt2; v0 = cs1; v1 = sn1; }
    else            { lam0 = rt2; lam1 = rt1; v0 = -sn1; v1 = cs1; }

    float a_n = 1.0f / sqrtf(fmaxf(lam0, 1e-12f));
    float b_n = 1.0f / sqrtf(fmaxf(lam1, 1e-12f));
    a_n = fmaxf(a_n, 1e-6f);
    float R = irisR[b];
    float z = fminf(fmaxf(R / a_n, 0.5f), 1000.0f);

    float rn = sqrtf(mu0 * mu0 + mu1 * mu1 + 1.0f) + 1e-8f;
    float icx = mu0 / rn * z, icy = mu1 / rn * z, icz = (1.0f / rn) * z;

    // tilt = acos(clip(b_n/a_n,0,1)): ctl = ratio, stl = sqrt(1-ctl^2)
    float ctl = fminf(fmaxf(b_n / a_n, 0.0f), 1.0f);
    float stl = sqrtf(fmaxf(1.0f - ctl * ctl, 0.0f));
    float hyp = sqrtf(v0 * v0 + v1 * v1);
    float kx = v0 / hyp, ky = v1 / hyp;
    // normal ∝ z*ctl + (k × z)*stl ; k·z = 0
    float nx = ky * stl, ny = -kx * stl, nz = ctl;
    float nn = sqrtf(nx * nx + ny * ny + nz * nz) + 1e-8f;
    nx /= nn; ny /= nn; nz /= nn;

    float px = icx + delta * nx, py = icy + delta * ny, pz = icz + delta * nz;

    out[448 + be * 3 + 0] = icx;
    out[448 + be * 3 + 1] = icy;
    out[448 + be * 3 + 2] = icz;
    out[640 + be * 3 + 0] = nx;
    out[640 + be * 3 + 1] = ny;
    out[640 + be * 3 + 2] = nz;
    out[832 + be * 3 + 0] = px;
    out[832 + be * 3 + 1] = py;
    out[832 + be * 3 + 2] = pz;
    out[1024 + be] = z;
}

// ---------------------------------------------------------------------------
// K4b: fc_out + geometry, one block (128 thr) per batch element
// ---------------------------------------------------------------------------
__global__ void k4b_head(const float* __restrict__ fow, const float* __restrict__ fob,
                         const float* __restrict__ Km, const float* __restrict__ irisR,
                         float* __restrict__ out) {
    int b = blockIdx.x;
    int tid = threadIdx.x;  // 128
    __shared__ float hs[HID];
    __shared__ float raws[OUTD];

    hs[tid] = g_h[b * HID + tid];
    hs[tid + 128] = g_h[b * HID + tid + 128];
    __syncthreads();

    int warp = tid >> 5, lane = tid & 31;
    for (int o = warp; o < OUTD; o += 4) {
        float part = 0.f;
#pragma unroll
        for (int k = 0; k < 8; k++) {
            int c = lane + 32 * k;
            part += hs[c] * fow[o * HID + c];
        }
        for (int off = 16; off; off >>= 1) part += __shfl_down_sync(0xffffffffu, part, off);
        if (lane == 0) raws[o] = part + fob[o];
    }
    __syncthreads();

    if (tid < 2) geometry(b, tid, raws, Km, irisR, out);
}

// ---------------------------------------------------------------------------
extern "C" void kernel_launch(void* const* d_in, const int* in_sizes, int n_in,
                              void* d_out, int out_size) {
    const float* x     = (const float*)d_in[0];
    const float* Km    = (const float*)d_in[1];
    const float* irisR = (const float*)d_in[2];
    const float* ca_w1 = (const float*)d_in[3];
    const float* ca_bn_g = (const float*)d_in[4];
    const float* ca_bn_b = (const float*)d_in[5];
    const float* ca_bn_m = (const float*)d_in[6];
    const float* ca_bn_v = (const float*)d_in[7];
    const float* ca_wh = (const float*)d_in[8];
    const float* ca_ww = (const float*)d_in[9];
    const float* fc1_w = (const float*)d_in[10];
    const float* fc1_b = (const float*)d_in[11];
    const float* bn1_g = (const float*)d_in[12];
    const float* bn1_b = (const float*)d_in[13];
    const float* bn1_m = (const float*)d_in[14];
    const float* bn1_v = (const float*)d_in[15];
    const float* fc_out_w = (const float*)d_in[16];
    const float* fc_out_b = (const float*)d_in[17];
    float* out = (float*)d_out;

    k1_rowcol<<<B * C, 256>>>(x);
    dim3 g2(B, 4);
    k2_squeeze<<<g2, 256>>>(ca_w1, ca_bn_g, ca_bn_b, ca_bn_m, ca_bn_v);
    k3_pool<<<B * C, 256>>>(x, ca_wh, ca_ww);
    dim3 g4(B, 8);
    k4a_fc1<<<g4, 256>>>(fc1_w, fc1_b, bn1_g, bn1_b, bn1_m, bn1_v);
    k4b_head<<<B, 128>>>(fc_out_w, fc_out_b, Km, irisR, out);
}